// round 15
// baseline (speedup 1.0000x reference)
#include <cuda_runtime.h>

typedef unsigned long long ull;

#define N_NODES 25000
#define N_EDGES 400000
#define F_IN    128
#define D_ATTR  16
#define H_DIM   64
#define HID     128
#define OUT_DIM 32
#define G_GRAPHS 64
#define EPG     16

// packed-weight buffer offsets (in ull)
#define OFF_PAB   0
#define OFF_E0    8192
#define OFF_E1    10752
#define OFF_N1    13312
#define OFF_PRT   19456
#define OFF_N1L1  23552
#define PACK_TOT  27648

// ---------------- scratch (device globals) -----------------------------------
__device__ __align__(16) ull   g_wpack[PACK_TOT];
__device__ __align__(16) float g_a[N_NODES * H_DIM];
__device__ __align__(16) float g_b[N_NODES * H_DIM];
__device__ __align__(16) float g_eagg[N_NODES * H_DIM];
__device__ __align__(16) float g_t[N_NODES * H_DIM];
__device__ __align__(16) float g_xn1[N_NODES * H_DIM];
__device__ __align__(16) float g_cusum[N_NODES * 3];
__device__ __align__(16) float g_deg[N_NODES];
__device__ __align__(16) float g_pos4a[N_NODES * 4];
__device__ __align__(16) float g_pos4b[N_NODES * 4];
__device__ __align__(16) float g_gsum[G_GRAPHS * H_DIM];
__device__ float g_fold[3 * 65 * H_DIM];

// ---------------- packed f32x2 helpers (sm_103a FFMA2) -----------------------
__device__ __forceinline__ ull fma2(ull a, ull b, ull c) {
    ull d;
    asm("fma.rn.f32x2 %0, %1, %2, %3;" : "=l"(d) : "l"(a), "l"(b), "l"(c));
    return d;
}
__device__ __forceinline__ ull pack2(float x, float y) {
    ull r; asm("mov.b64 %0, {%1, %2};" : "=l"(r) : "f"(x), "f"(y)); return r;
}
__device__ __forceinline__ float2 unpack2(ull v) {
    float lo, hi; asm("mov.b64 {%0, %1}, %2;" : "=f"(lo), "=f"(hi) : "l"(v));
    return make_float2(lo, hi);
}
__device__ __forceinline__ void red_add_v2(float* a, float x, float y) {
    asm volatile("red.global.add.v2.f32 [%0], {%1, %2};"
                 :: "l"(a), "f"(x), "f"(y) : "memory");
}
__device__ __forceinline__ float silu_f(float v) {
    float t;
    asm("tanh.approx.f32 %0, %1;" : "=f"(t) : "f"(0.5f * v));
    float hv = 0.5f * v;
    return fmaf(hv, t, hv);
}

// ---------------- fold prep ----------------------------------------------------
__global__ void prep_fold(const float* __restrict__ nw2_0,
                          const float* __restrict__ nb2_0,
                          const float* __restrict__ mlp_w1,
                          const float* __restrict__ nw1_1,
                          float* __restrict__ fold) {
    int m = blockIdx.y;
    const float* W = (m == 0) ? mlp_w1 : (m == 1) ? (mlp_w1 + 128 * H_DIM) : nw1_1;
    int row = blockIdx.x;
    int c = threadIdx.x;
    float s = 0.f;
    if (row < 64) {
#pragma unroll 8
        for (int j = 0; j < 128; j++) s += nw2_0[row * HID + j] * W[j * H_DIM + c];
    } else {
#pragma unroll 8
        for (int j = 0; j < 128; j++) s += nb2_0[j] * W[j * H_DIM + c];
    }
    fold[(m * 65 + row) * H_DIM + c] = s;
}

// ---------------- pack_all ------------------------------------------------------
__device__ __forceinline__ void pack_sec(ull* __restrict__ dst,
                                         const float* __restrict__ W,
                                         int nkp, int tid, int T) {
    for (int i = tid; i < nkp * 64; i += T) {
        int kp = i >> 6, c = i & 63;
        dst[i] = pack2(W[(2 * kp) * H_DIM + c], W[(2 * kp + 1) * H_DIM + c]);
    }
}

__global__ void pack_all(const float* __restrict__ mlp_w0,
                         const float* __restrict__ mlp_w1,
                         const float* __restrict__ edge_w0,
                         const float* __restrict__ edge_w1,
                         const float* __restrict__ nw1_0,
                         const float* __restrict__ nw1_1,
                         const float* __restrict__ fold,
                         const float* __restrict__ pos,
                         ull* __restrict__ wp,
                         float* __restrict__ pos4,
                         float* __restrict__ eagg,
                         float* __restrict__ cusum,
                         float* __restrict__ deg,
                         float* __restrict__ gsum) {
    int tid = blockIdx.x * blockDim.x + threadIdx.x;
    int T = gridDim.x * blockDim.x;

    pack_sec(wp + OFF_PAB,         mlp_w0,               64, tid, T);
    pack_sec(wp + OFF_PAB + 4096,  mlp_w0 + 128 * H_DIM, 64, tid, T);
    pack_sec(wp + OFF_E0,          edge_w0,              32, tid, T);
    pack_sec(wp + OFF_E0 + 2048,   mlp_w0 + 256 * H_DIM,  8, tid, T);
    pack_sec(wp + OFF_E1,          edge_w1,              32, tid, T);
    pack_sec(wp + OFF_E1 + 2048,   mlp_w1 + 256 * H_DIM,  8, tid, T);
    pack_sec(wp + OFF_N1,          nw1_0,                96, tid, T);
    pack_sec(wp + OFF_PRT,         fold,                 32, tid, T);
    pack_sec(wp + OFF_PRT + 2048,  fold + 65 * H_DIM,    32, tid, T);
    pack_sec(wp + OFF_N1L1,        fold + 130 * H_DIM,   32, tid, T);
    pack_sec(wp + OFF_N1L1 + 2048, nw1_1 + 128 * H_DIM,  32, tid, T);

    for (int i = tid; i < N_NODES; i += T)
        *(float4*)(pos4 + 4 * i) = make_float4(pos[3*i], pos[3*i+1], pos[3*i+2], 0.f);

    float4 z4 = make_float4(0.f, 0.f, 0.f, 0.f);
    for (int i = tid; i < (N_NODES * H_DIM) / 4; i += T) ((float4*)eagg)[i] = z4;
    for (int i = tid; i < (N_NODES * 3) / 4; i += T)     ((float4*)cusum)[i] = z4;
    for (int i = tid; i < N_NODES / 4; i += T)           ((float4*)deg)[i] = z4;
    for (int i = tid; i < (G_GRAPHS * H_DIM) / 4; i += T) ((float4*)gsum)[i] = z4;
}

// ---------------- smem weight copy ---------------------------------------------
__device__ __forceinline__ void copy_w(ull* s, const ull* g, int n_ull) {
    const ulonglong2* src = (const ulonglong2*)g;
    ulonglong2* dst = (ulonglong2*)s;
    for (int i = threadIdx.x; i < (n_ull >> 1); i += 256) dst[i] = src[i];
    __syncthreads();
}

// ---------------- layer-0 precompute: a=x@Wd, b=x@Ws, xn1=x@W1x ---------------
__global__ void __launch_bounds__(256, 2) precompute_ab(const float* __restrict__ x,
                                                        const ull* __restrict__ wpack,
                                                        float* __restrict__ a,
                                                        float* __restrict__ b,
                                                        float* __restrict__ xn1) {
    extern __shared__ ull swp[];                  // 12288 ull = 96KB
    {
        const ulonglong2* s1 = (const ulonglong2*)(wpack + OFF_PAB);
        ulonglong2* d1 = (ulonglong2*)swp;
        for (int i = threadIdx.x; i < 4096; i += 256) d1[i] = s1[i];
        const ulonglong2* s2 = (const ulonglong2*)(wpack + OFF_N1);
        ulonglong2* d2 = (ulonglong2*)(swp + 8192);
        for (int i = threadIdx.x; i < 2048; i += 256) d2[i] = s2[i];
        __syncthreads();
    }

    int lane = threadIdx.x & 31;
    int warp = (blockIdx.x * 256 + threadIdx.x) >> 5;
    int nw = gridDim.x * 8;
    const int NG = N_NODES / 4;
    const ull* s_wd = swp;
    const ull* s_ws = swp + 4096;
    const ull* s_wn = swp + 8192;

    for (int g = warp; g < NG; g += nw) {
        int nbase = g * 4;
        ull aC0[4], aC1[4], bC0[4], bC1[4], cC0[4], cC1[4];
#pragma unroll
        for (int t = 0; t < 4; t++) { aC0[t]=0; aC1[t]=0; bC0[t]=0; bC1[t]=0; cC0[t]=0; cC1[t]=0; }
#pragma unroll 4
        for (int q = 0; q < 32; q++) {
            ulonglong2 wd0 = *(const ulonglong2*)(s_wd + (2*q)   * 64 + 2*lane);
            ulonglong2 wd1 = *(const ulonglong2*)(s_wd + (2*q+1) * 64 + 2*lane);
            ulonglong2 ws0 = *(const ulonglong2*)(s_ws + (2*q)   * 64 + 2*lane);
            ulonglong2 ws1 = *(const ulonglong2*)(s_ws + (2*q+1) * 64 + 2*lane);
            ulonglong2 wn0 = *(const ulonglong2*)(s_wn + (2*q)   * 64 + 2*lane);
            ulonglong2 wn1 = *(const ulonglong2*)(s_wn + (2*q+1) * 64 + 2*lane);
#pragma unroll
            for (int t = 0; t < 4; t++) {
                ulonglong2 xp = *(const ulonglong2*)(x + (size_t)(nbase + t) * F_IN + 4 * q);
                aC0[t] = fma2(xp.x, wd0.x, aC0[t]); aC1[t] = fma2(xp.x, wd0.y, aC1[t]);
                aC0[t] = fma2(xp.y, wd1.x, aC0[t]); aC1[t] = fma2(xp.y, wd1.y, aC1[t]);
                bC0[t] = fma2(xp.x, ws0.x, bC0[t]); bC1[t] = fma2(xp.x, ws0.y, bC1[t]);
                bC0[t] = fma2(xp.y, ws1.x, bC0[t]); bC1[t] = fma2(xp.y, ws1.y, bC1[t]);
                cC0[t] = fma2(xp.x, wn0.x, cC0[t]); cC1[t] = fma2(xp.x, wn0.y, cC1[t]);
                cC0[t] = fma2(xp.y, wn1.x, cC0[t]); cC1[t] = fma2(xp.y, wn1.y, cC1[t]);
            }
        }
#pragma unroll
        for (int t = 0; t < 4; t++) {
            float2 va0 = unpack2(aC0[t]), va1 = unpack2(aC1[t]);
            float2 vb0 = unpack2(bC0[t]), vb1 = unpack2(bC1[t]);
            float2 vc0 = unpack2(cC0[t]), vc1 = unpack2(cC1[t]);
            *(float2*)(a + (size_t)(nbase + t) * H_DIM + 2*lane) =
                make_float2(va0.x + va0.y, va1.x + va1.y);
            *(float2*)(b + (size_t)(nbase + t) * H_DIM + 2*lane) =
                make_float2(vb0.x + vb0.y, vb1.x + vb1.y);
            *(float2*)(xn1 + (size_t)(nbase + t) * H_DIM + 2*lane) =
                make_float2(vc0.x + vc0.y, vc1.x + vc1.y);
        }
    }
}

// ---------------- layer-1 fused precompute: a1, b1, pos, zero ------------------
__global__ void __launch_bounds__(256, 3) precompute_t(const float* __restrict__ tin,
                                                       const ull* __restrict__ wpack,
                                                       const float* __restrict__ fold,
                                                       const float* __restrict__ posin,
                                                       const float* __restrict__ cusum,
                                                       const float* __restrict__ deg,
                                                       float* __restrict__ a,
                                                       float* __restrict__ b,
                                                       float* __restrict__ posout,
                                                       float* __restrict__ eagg) {
    extern __shared__ ull swp[];                  // 4096 ull = 32KB
    copy_w(swp, wpack + OFF_PRT, 4096);

    int lane = threadIdx.x & 31;
    int warp = (blockIdx.x * 256 + threadIdx.x) >> 5;
    int nw = gridDim.x * 8;
    float ba0 = fold[64 * H_DIM + 2*lane],        ba1 = fold[64 * H_DIM + 2*lane + 1];
    float bb0 = fold[(65 + 64) * H_DIM + 2*lane], bb1 = fold[(65 + 64) * H_DIM + 2*lane + 1];
    const int NG = N_NODES / 4;

    for (int g = warp; g < NG; g += nw) {
        int nbase = g * 4;
        ull aC0[4], aC1[4], bC0[4], bC1[4];
#pragma unroll
        for (int t = 0; t < 4; t++) { aC0[t]=0; aC1[t]=0; bC0[t]=0; bC1[t]=0; }
#pragma unroll 4
        for (int q = 0; q < 16; q++) {
            ulonglong2 wa0 = *(const ulonglong2*)(swp + (2*q)   * 64 + 2*lane);
            ulonglong2 wa1 = *(const ulonglong2*)(swp + (2*q+1) * 64 + 2*lane);
            ulonglong2 wb0 = *(const ulonglong2*)(swp + 2048 + (2*q)   * 64 + 2*lane);
            ulonglong2 wb1 = *(const ulonglong2*)(swp + 2048 + (2*q+1) * 64 + 2*lane);
#pragma unroll
            for (int t = 0; t < 4; t++) {
                ulonglong2 tp = *(const ulonglong2*)(tin + (size_t)(nbase + t) * H_DIM + 4 * q);
                aC0[t] = fma2(tp.x, wa0.x, aC0[t]); aC1[t] = fma2(tp.x, wa0.y, aC1[t]);
                aC0[t] = fma2(tp.y, wa1.x, aC0[t]); aC1[t] = fma2(tp.y, wa1.y, aC1[t]);
                bC0[t] = fma2(tp.x, wb0.x, bC0[t]); bC1[t] = fma2(tp.x, wb0.y, bC1[t]);
                bC0[t] = fma2(tp.y, wb1.x, bC0[t]); bC1[t] = fma2(tp.y, wb1.y, bC1[t]);
            }
        }
#pragma unroll
        for (int t = 0; t < 4; t++) {
            float2 va0 = unpack2(aC0[t]), va1 = unpack2(aC1[t]);
            float2 vb0 = unpack2(bC0[t]), vb1 = unpack2(bC1[t]);
            *(float2*)(a + (size_t)(nbase + t) * H_DIM + 2*lane) =
                make_float2(ba0 + va0.x + va0.y, ba1 + va1.x + va1.y);
            *(float2*)(b + (size_t)(nbase + t) * H_DIM + 2*lane) =
                make_float2(bb0 + vb0.x + vb0.y, bb1 + vb1.x + vb1.y);
            *(float2*)(eagg + (size_t)(nbase + t) * H_DIM + 2*lane) = make_float2(0.f, 0.f);
        }
        if (lane < 4) {
            int node = nbase + lane;
            float dg = fmaxf(deg[node], 1.0f);
            float4 pv = *(const float4*)(posin + 4 * node);
            *(float4*)(posout + 4 * node) = make_float4(
                pv.x + cusum[node * 3 + 0] / dg,
                pv.y + cusum[node * 3 + 1] / dg,
                pv.z + cusum[node * 3 + 2] / dg, 0.f);
        }
    }
}

// ---------------- edge kernel: R12 form + double-buffered attr/eidx prefetch --
__device__ __forceinline__ void stage_group(int ebase,
                                            float* s_ea, int* s_ei,
                                            const float* __restrict__ edge_attr,
                                            const int* __restrict__ eidx,
                                            int lane) {
    const float4* gattr = (const float4*)(edge_attr + (size_t)ebase * D_ATTR);
    ((float4*)s_ea)[lane]      = gattr[lane];
    ((float4*)s_ea)[lane + 32] = gattr[lane + 32];
    if (lane < 4)
        ((int4*)s_ei)[lane] = *(const int4*)(eidx + ebase + 4 * lane);
    else if (lane < 8)
        ((int4*)s_ei)[lane] = *(const int4*)(eidx + N_EDGES + ebase + 4 * (lane - 4));
}

template<int DO_COORD>
__global__ void __launch_bounds__(256, 2) edge_kernel(const float* __restrict__ pos4,
                                                      const int* __restrict__ eidx,
                                                      const float* __restrict__ edge_attr,
                                                      const ull* __restrict__ wpack,
                                                      const float* __restrict__ mlp_w,
                                                      const float* __restrict__ edge_b,
                                                      const float* __restrict__ coord_w,
                                                      const float* __restrict__ coord_b,
                                                      const float* __restrict__ a,
                                                      const float* __restrict__ b,
                                                      float* __restrict__ eagg,
                                                      float* __restrict__ cusum,
                                                      float* __restrict__ deg) {
    extern __shared__ ull sm_u[];
    ull* s_wp     = sm_u;                          // 2048 ull: edge_w kpacked
    ull* s_wattrP = sm_u + 2048;                   // 512 ull: W_attr kpacked
    float* s_hall = (float*)(sm_u + 2560);         // 8 warps * EPG*64 floats (32KB)
    float* s_eall = s_hall + 8 * EPG * H_DIM;      // 8 warps * 2 * EPG*16 floats (16KB)
    int*   s_iall = (int*)(s_eall + 8 * 2 * EPG * D_ATTR); // 8 warps * 2 * 32 ints (2KB)
    copy_w(sm_u, wpack, 2560);

    int lane = threadIdx.x & 31, k0 = lane * 2;
    int wl = threadIdx.x >> 5;
    int warp = (blockIdx.x * 256 + threadIdx.x) >> 5;
    int nw = gridDim.x * 8;
    float* s_h   = s_hall + wl * (EPG * H_DIM);
    float* s_eaB = s_eall + wl * (2 * EPG * D_ATTR);   // two buffers of EPG*16
    int*   s_eiB = s_iall + wl * (2 * 32);             // two buffers of 32 ints

    float wr0 = mlp_w[(2 * F_IN + D_ATTR) * H_DIM + k0];
    float wr1 = mlp_w[(2 * F_IN + D_ATTR) * H_DIM + k0 + 1];
    float eb0 = edge_b[k0], eb1 = edge_b[k0 + 1];
    float cw0 = coord_w[k0], cw1 = coord_w[k0 + 1];
    float cb = coord_b[0];

    const int NGROUPS = N_EDGES / EPG;             // 25000
    int g = warp;
    if (g < NGROUPS) stage_group(g * EPG, s_eaB, s_eiB, edge_attr, eidx, lane);
    int parity = 0;

    for (; g < NGROUPS; g += nw) {
        __syncwarp();                              // staged buffer visible
        float* s_ea = s_eaB + parity * (EPG * D_ATTR);
        int*   s_ei = s_eiB + parity * 32;

        // prefetch next group into the other buffer (overlaps this group's compute)
        int gn = g + nw;
        if (gn < NGROUPS)
            stage_group(gn * EPG, s_eaB + (parity ^ 1) * (EPG * D_ATTR),
                        s_eiB + (parity ^ 1) * 32, edge_attr, eidx, lane);

        int dsts[EPG];
        float mydx = 0.f, mydy = 0.f, mydz = 0.f;

        // ---- phase 1: per-edge h in 4 batches of 4
#pragma unroll
        for (int half = 0; half < 4; half++) {
            int4 s4 = ((const int4*)s_ei)[half];
            int4 d4 = ((const int4*)s_ei)[4 + half];
            int ss[4] = {s4.x, s4.y, s4.z, s4.w};
            int dd[4] = {d4.x, d4.y, d4.z, d4.w};
            dsts[4*half+0] = d4.x; dsts[4*half+1] = d4.y;
            dsts[4*half+2] = d4.z; dsts[4*half+3] = d4.w;
            float b0[4], b1[4];
            ull hk0[4], hk1[4];
#pragma unroll
            for (int t = 0; t < 4; t++) {
                int ei = half * 4 + t;
                float4 pd = *(const float4*)(pos4 + 4 * dd[t]);
                float4 ps = *(const float4*)(pos4 + 4 * ss[t]);
                float dx = pd.x - ps.x, dy = pd.y - ps.y, dz = pd.z - ps.z;
                if (lane == ei) { mydx = dx; mydy = dy; mydz = dz; }
                float radial = dx * dx + dy * dy + dz * dz;
                float2 av = *(const float2*)(a + (size_t)dd[t] * H_DIM + k0);
                float2 bv = *(const float2*)(b + (size_t)ss[t] * H_DIM + k0);
                b0[t] = av.x + bv.x + radial * wr0;
                b1[t] = av.y + bv.y + radial * wr1;
                hk0[t] = 0; hk1[t] = 0;
            }
#pragma unroll
            for (int q = 0; q < 2; q++) {
                ulonglong2 w0 = *(const ulonglong2*)(s_wattrP + (4*q+0)*64 + 2*lane);
                ulonglong2 w1 = *(const ulonglong2*)(s_wattrP + (4*q+1)*64 + 2*lane);
                ulonglong2 w2 = *(const ulonglong2*)(s_wattrP + (4*q+2)*64 + 2*lane);
                ulonglong2 w3 = *(const ulonglong2*)(s_wattrP + (4*q+3)*64 + 2*lane);
#pragma unroll
                for (int t = 0; t < 4; t++) {
                    int ei = half * 4 + t;
                    ulonglong2 eaA = *(const ulonglong2*)(s_ea + ei * D_ATTR + 8*q);
                    ulonglong2 eaB = *(const ulonglong2*)(s_ea + ei * D_ATTR + 8*q + 4);
                    hk0[t] = fma2(eaA.x, w0.x, hk0[t]); hk1[t] = fma2(eaA.x, w0.y, hk1[t]);
                    hk0[t] = fma2(eaA.y, w1.x, hk0[t]); hk1[t] = fma2(eaA.y, w1.y, hk1[t]);
                    hk0[t] = fma2(eaB.x, w2.x, hk0[t]); hk1[t] = fma2(eaB.x, w2.y, hk1[t]);
                    hk0[t] = fma2(eaB.y, w3.x, hk0[t]); hk1[t] = fma2(eaB.y, w3.y, hk1[t]);
                }
            }
#pragma unroll
            for (int t = 0; t < 4; t++) {
                float2 v0 = unpack2(hk0[t]), v1 = unpack2(hk1[t]);
                float h0 = silu_f(b0[t] + v0.x + v0.y);
                float h1 = silu_f(b1[t] + v1.x + v1.y);
                *(float2*)(s_h + (half * 4 + t) * H_DIM + k0) = make_float2(h0, h1);
            }
        }
        __syncwarp();

        // ---- phase 2: e = silu(h @ edge_w + eb)
        ull acc0[EPG], acc1[EPG];
#pragma unroll
        for (int t = 0; t < EPG; t++) { acc0[t] = 0; acc1[t] = 0; }
#pragma unroll 2
        for (int q = 0; q < 16; q++) {
            ulonglong2 wA = *(const ulonglong2*)(s_wp + (2*q)   * 64 + 2*lane);
            ulonglong2 wB = *(const ulonglong2*)(s_wp + (2*q+1) * 64 + 2*lane);
#pragma unroll
            for (int t = 0; t < EPG; t++) {
                ulonglong2 hv = *(const ulonglong2*)(s_h + t * H_DIM + 4 * q);
                acc0[t] = fma2(hv.x, wA.x, acc0[t]); acc1[t] = fma2(hv.x, wA.y, acc1[t]);
                acc0[t] = fma2(hv.y, wB.x, acc0[t]); acc1[t] = fma2(hv.y, wB.y, acc1[t]);
            }
        }
        __syncwarp();

        // ---- epilogue
        float myss = 0.f;
#pragma unroll
        for (int t = 0; t < EPG; t++) {
            float2 v0 = unpack2(acc0[t]), v1 = unpack2(acc1[t]);
            float e0 = silu_f(eb0 + v0.x + v0.y);
            float e1 = silu_f(eb1 + v1.x + v1.y);
            red_add_v2(eagg + (size_t)dsts[t] * H_DIM + k0, e0, e1);
            if (DO_COORD) {
                float p = e0 * cw0 + e1 * cw1;
                p += __shfl_xor_sync(0xffffffffu, p, 16);
                p += __shfl_xor_sync(0xffffffffu, p, 8);
                p += __shfl_xor_sync(0xffffffffu, p, 4);
                p += __shfl_xor_sync(0xffffffffu, p, 2);
                p += __shfl_xor_sync(0xffffffffu, p, 1);
                if (lane == t) myss = silu_f(p + cb);
            }
        }
        if (DO_COORD && lane < EPG) {
            int d3 = dsts[lane] * 3;
            atomicAdd(cusum + d3 + 0, mydx * myss);
            atomicAdd(cusum + d3 + 1, mydy * myss);
            atomicAdd(cusum + d3 + 2, mydz * myss);
            atomicAdd(deg + dsts[lane], 1.0f);
        }
        parity ^= 1;
    }
}

// ---------------- node1 layer 0 (slim): t = silu(xn1 + eagg@W1e + b1) ---------
__global__ void __launch_bounds__(256, 3) node1_kernel(const float* __restrict__ xn1,
                                                       const float* __restrict__ eagg,
                                                       const ull* __restrict__ wpack,
                                                       const float* __restrict__ nb1,
                                                       float* __restrict__ tout) {
    extern __shared__ ull s_w1p[];                 // 2048 ull = 16KB
    copy_w(s_w1p, wpack + OFF_N1 + 4096, 2048);

    int lane = threadIdx.x & 31;
    int warp = (blockIdx.x * 256 + threadIdx.x) >> 5;
    int nw = gridDim.x * 8;
    float nb0 = nb1[2 * lane], nbx1 = nb1[2 * lane + 1];
    const int NG = N_NODES / 8;

    for (int g = warp; g < NG; g += nw) {
        int nbase = g * 8;
        ull a0[8], a1[8];
#pragma unroll
        for (int t = 0; t < 8; t++) { a0[t] = 0; a1[t] = 0; }
#pragma unroll 4
        for (int q = 0; q < 16; q++) {
            ulonglong2 w0 = *(const ulonglong2*)(s_w1p + (2*q)   * 64 + 2*lane);
            ulonglong2 w1 = *(const ulonglong2*)(s_w1p + (2*q+1) * 64 + 2*lane);
#pragma unroll
            for (int t = 0; t < 8; t++) {
                ulonglong2 ep = *(const ulonglong2*)(eagg + (size_t)(nbase + t) * H_DIM + 4 * q);
                a0[t] = fma2(ep.x, w0.x, a0[t]); a1[t] = fma2(ep.x, w0.y, a1[t]);
                a0[t] = fma2(ep.y, w1.x, a0[t]); a1[t] = fma2(ep.y, w1.y, a1[t]);
            }
        }
#pragma unroll
        for (int t = 0; t < 8; t++) {
            float2 xv = *(const float2*)(xn1 + (size_t)(nbase + t) * H_DIM + 2*lane);
            float2 v0 = unpack2(a0[t]), v1 = unpack2(a1[t]);
            *(float2*)(tout + (size_t)(nbase + t) * H_DIM + 2*lane) =
                make_float2(silu_f(nb0 + xv.x + v0.x + v0.y),
                            silu_f(nbx1 + xv.y + v1.x + v1.y));
        }
    }
}

// ---------------- node1 layer 1 + fused pooling -------------------------------
__global__ void __launch_bounds__(256, 3) node1_l1_pool(const float* __restrict__ tin,
                                                        const float* __restrict__ eagg,
                                                        const ull* __restrict__ wpack,
                                                        const float* __restrict__ fold,
                                                        const float* __restrict__ nb1_1,
                                                        const int* __restrict__ batch,
                                                        float* __restrict__ gsum) {
    extern __shared__ ull swp[];                   // 4096 ull = 32KB
    copy_w(swp, wpack + OFF_N1L1, 4096);

    int lane = threadIdx.x & 31;
    int warp = (blockIdx.x * 256 + threadIdx.x) >> 5;
    int nw = gridDim.x * 8;
    float bn0 = fold[(130 + 64) * H_DIM + 2*lane]     + nb1_1[2*lane];
    float bn1 = fold[(130 + 64) * H_DIM + 2*lane + 1] + nb1_1[2*lane + 1];
    const int NG = N_NODES / 8;

    for (int g = warp; g < NG; g += nw) {
        int nbase = g * 8;
        ull a0[8], a1[8];
#pragma unroll
        for (int t = 0; t < 8; t++) { a0[t] = 0; a1[t] = 0; }
#pragma unroll 4
        for (int q = 0; q < 16; q++) {
            ulonglong2 w0 = *(const ulonglong2*)(swp + (2*q)   * 64 + 2*lane);
            ulonglong2 w1 = *(const ulonglong2*)(swp + (2*q+1) * 64 + 2*lane);
#pragma unroll
            for (int t = 0; t < 8; t++) {
                ulonglong2 tp = *(const ulonglong2*)(tin + (size_t)(nbase + t) * H_DIM + 4 * q);
                a0[t] = fma2(tp.x, w0.x, a0[t]); a1[t] = fma2(tp.x, w0.y, a1[t]);
                a0[t] = fma2(tp.y, w1.x, a0[t]); a1[t] = fma2(tp.y, w1.y, a1[t]);
            }
        }
#pragma unroll 4
        for (int q = 0; q < 16; q++) {
            ulonglong2 w0 = *(const ulonglong2*)(swp + 2048 + (2*q)   * 64 + 2*lane);
            ulonglong2 w1 = *(const ulonglong2*)(swp + 2048 + (2*q+1) * 64 + 2*lane);
#pragma unroll
            for (int t = 0; t < 8; t++) {
                ulonglong2 ep = *(const ulonglong2*)(eagg + (size_t)(nbase + t) * H_DIM + 4 * q);
                a0[t] = fma2(ep.x, w0.x, a0[t]); a1[t] = fma2(ep.x, w0.y, a1[t]);
                a0[t] = fma2(ep.y, w1.x, a0[t]); a1[t] = fma2(ep.y, w1.y, a1[t]);
            }
        }
        int bfirst = batch[nbase], blast = batch[nbase + 7];
        if (bfirst == blast) {
            float s0 = 0.f, s1 = 0.f;
#pragma unroll
            for (int t = 0; t < 8; t++) {
                float2 v0 = unpack2(a0[t]), v1 = unpack2(a1[t]);
                s0 += silu_f(bn0 + v0.x + v0.y);
                s1 += silu_f(bn1 + v1.x + v1.y);
            }
            red_add_v2(gsum + bfirst * H_DIM + 2 * lane, s0, s1);
        } else {
#pragma unroll
            for (int t = 0; t < 8; t++) {
                float2 v0 = unpack2(a0[t]), v1 = unpack2(a1[t]);
                float t0 = silu_f(bn0 + v0.x + v0.y);
                float t1 = silu_f(bn1 + v1.x + v1.y);
                red_add_v2(gsum + batch[nbase + t] * H_DIM + 2 * lane, t0, t1);
            }
        }
    }
}

// ---------------- final: count + fold layer1 w2 + output MLP ------------------
__global__ void final_kernel(const float* __restrict__ gsum,
                             const int* __restrict__ batch,
                             const float* __restrict__ nw2,
                             const float* __restrict__ nb2,
                             const float* __restrict__ w1,
                             const float* __restrict__ b1,
                             const float* __restrict__ w2,
                             const float* __restrict__ b2,
                             float* __restrict__ out) {
    int g = blockIdx.x;
    int tx = threadIdx.x;   // 128 threads
    __shared__ float sm64[H_DIM];
    __shared__ float sg[HID];
    __shared__ float st[HID];
    __shared__ int scnt;
    if (tx == 0) scnt = 0;
    __syncthreads();
    int local = 0;
    for (int i = tx; i < N_NODES; i += 128) local += (batch[i] == g);
#pragma unroll
    for (int off = 16; off; off >>= 1) local += __shfl_xor_sync(0xffffffffu, local, off);
    if ((tx & 31) == 0) atomicAdd(&scnt, local);
    __syncthreads();
    float cnt = fmaxf((float)scnt, 1.0f);
    if (tx < H_DIM) sm64[tx] = gsum[g * H_DIM + tx] / cnt;
    __syncthreads();
    float gv = nb2[tx];
#pragma unroll 8
    for (int k = 0; k < H_DIM; k++) gv += sm64[k] * nw2[k * HID + tx];
    sg[tx] = fmaxf(gv, 0.0f);
    __syncthreads();
    float acc = b1[tx];
#pragma unroll 8
    for (int j = 0; j < HID; j++) acc += sg[j] * w1[j * HID + tx];
    st[tx] = fmaxf(acc, 0.0f);
    __syncthreads();
    if (tx < OUT_DIM) {
        float o = b2[tx];
#pragma unroll 8
        for (int k = 0; k < HID; k++) o += st[k] * w2[k * OUT_DIM + tx];
        out[g * OUT_DIM + tx] = o;
    }
}

// ---------------- launch --------------------------------------------------------
extern "C" void kernel_launch(void* const* d_in, const int* in_sizes, int n_in,
                              void* d_out, int out_size) {
    const float* x         = (const float*)d_in[0];
    const float* pos       = (const float*)d_in[1];
    const float* edge_attr = (const float*)d_in[2];
    const int* eidx        = (const int*)d_in[3];
    const int* batch       = (const int*)d_in[4];

    const float* mlp_w[2]  = {(const float*)d_in[5],  (const float*)d_in[14]};
    const float* edge_w[2] = {(const float*)d_in[6],  (const float*)d_in[15]};
    const float* edge_b[2] = {(const float*)d_in[7],  (const float*)d_in[16]};
    const float* coord_w[2]= {(const float*)d_in[8],  (const float*)d_in[17]};
    const float* coord_b[2]= {(const float*)d_in[9],  (const float*)d_in[18]};
    const float* nw1[2]    = {(const float*)d_in[10], (const float*)d_in[19]};
    const float* nb1[2]    = {(const float*)d_in[11], (const float*)d_in[20]};
    const float* nw2[2]    = {(const float*)d_in[12], (const float*)d_in[21]};
    const float* nb2[2]    = {(const float*)d_in[13], (const float*)d_in[22]};
    const float* ow1 = (const float*)d_in[23];
    const float* ob1 = (const float*)d_in[24];
    const float* ow2 = (const float*)d_in[25];
    const float* ob2 = (const float*)d_in[26];
    float* out = (float*)d_out;

    float *pa, *pb, *pe, *pt, *pxn, *pc, *pd, *pp4a, *pp4b, *pgs, *pf;
    ull* pw;
    cudaGetSymbolAddress((void**)&pa, g_a);
    cudaGetSymbolAddress((void**)&pb, g_b);
    cudaGetSymbolAddress((void**)&pe, g_eagg);
    cudaGetSymbolAddress((void**)&pt, g_t);
    cudaGetSymbolAddress((void**)&pxn, g_xn1);
    cudaGetSymbolAddress((void**)&pc, g_cusum);
    cudaGetSymbolAddress((void**)&pd, g_deg);
    cudaGetSymbolAddress((void**)&pp4a, g_pos4a);
    cudaGetSymbolAddress((void**)&pp4b, g_pos4b);
    cudaGetSymbolAddress((void**)&pgs, g_gsum);
    cudaGetSymbolAddress((void**)&pf, g_fold);
    cudaGetSymbolAddress((void**)&pw, g_wpack);

    const int PRE_SMEM  = 12288 * (int)sizeof(ull);  // 96KB
    const int PRT_SMEM  = 4096 * (int)sizeof(ull);   // 32KB
    const int N1_SMEM   = 2048 * (int)sizeof(ull);   // 16KB
    const int N1L1_SMEM = 4096 * (int)sizeof(ull);   // 32KB
    const int EDGE_SMEM = 2560 * (int)sizeof(ull)
                        + 8 * EPG * H_DIM * (int)sizeof(float)        // h staging
                        + 8 * 2 * EPG * D_ATTR * (int)sizeof(float)   // attr dbl-buf
                        + 8 * 2 * 32 * (int)sizeof(int);              // eidx dbl-buf (~70KB)
    cudaFuncSetAttribute(precompute_ab, cudaFuncAttributeMaxDynamicSharedMemorySize, PRE_SMEM);
    cudaFuncSetAttribute(precompute_t, cudaFuncAttributeMaxDynamicSharedMemorySize, PRT_SMEM);
    cudaFuncSetAttribute(node1_kernel, cudaFuncAttributeMaxDynamicSharedMemorySize, N1_SMEM);
    cudaFuncSetAttribute(node1_l1_pool, cudaFuncAttributeMaxDynamicSharedMemorySize, N1L1_SMEM);
    cudaFuncSetAttribute(edge_kernel<1>, cudaFuncAttributeMaxDynamicSharedMemorySize, EDGE_SMEM);
    cudaFuncSetAttribute(edge_kernel<0>, cudaFuncAttributeMaxDynamicSharedMemorySize, EDGE_SMEM);

    // ---------------- prep: 2 launches total
    prep_fold<<<dim3(65, 3), 64>>>(nw2[0], nb2[0], mlp_w[1], nw1[1], pf);
    pack_all<<<256, 256>>>(mlp_w[0], mlp_w[1], edge_w[0], edge_w[1], nw1[0], nw1[1],
                           pf, pos, pw, pp4a, pe, pc, pd, pgs);

    // ---------------- layer 0
    precompute_ab<<<296, 256, PRE_SMEM>>>(x, pw, pa, pb, pxn);
    edge_kernel<1><<<296, 256, EDGE_SMEM>>>(pp4a, eidx, edge_attr, pw + OFF_E0, mlp_w[0],
                                            edge_b[0], coord_w[0], coord_b[0],
                                            pa, pb, pe, pc, pd);
    node1_kernel<<<444, 256, N1_SMEM>>>(pxn, pe, pw, nb1[0], pt);

    // ---------------- layer 1
    precompute_t<<<444, 256, PRT_SMEM>>>(pt, pw, pf, pp4a, pc, pd, pa, pb, pp4b, pe);
    edge_kernel<0><<<296, 256, EDGE_SMEM>>>(pp4b, eidx, edge_attr, pw + OFF_E1, mlp_w[1],
                                            edge_b[1], coord_w[1], coord_b[1],
                                            pa, pb, pe, pc, pd);
    node1_l1_pool<<<444, 256, N1L1_SMEM>>>(pt, pe, pw, pf, nb1[1], batch, pgs);

    // ---------------- output
    final_kernel<<<G_GRAPHS, HID>>>(pgs, batch, nw2[1], nb2[1], ow1, ob1, ow2, ob2, out);
}

// round 16
// speedup vs baseline: 1.0605x; 1.0605x over previous
#include <cuda_runtime.h>

typedef unsigned long long ull;

#define N_NODES 25000
#define N_EDGES 400000
#define F_IN    128
#define D_ATTR  16
#define H_DIM   64
#define HID     128
#define OUT_DIM 32
#define G_GRAPHS 64
#define EPG     16

// packed-weight buffer offsets (in ull)
#define OFF_PAB   0
#define OFF_E0    8192
#define OFF_E1    10752
#define OFF_N1    13312
#define OFF_PRT   19456
#define OFF_N1L1  23552
#define PACK_TOT  27648

// ---------------- scratch (device globals) -----------------------------------
__device__ __align__(16) ull   g_wpack[PACK_TOT];
__device__ __align__(16) float g_a[N_NODES * H_DIM];
__device__ __align__(16) float g_b[N_NODES * H_DIM];
__device__ __align__(16) float g_eagg[N_NODES * H_DIM];
__device__ __align__(16) float g_t[N_NODES * H_DIM];
__device__ __align__(16) float g_xn1[N_NODES * H_DIM];
__device__ __align__(16) float g_cusum[N_NODES * 3];
__device__ __align__(16) float g_deg[N_NODES];
__device__ __align__(16) float g_pos4a[N_NODES * 4];
__device__ __align__(16) float g_pos4b[N_NODES * 4];
__device__ __align__(16) float g_gsum[G_GRAPHS * H_DIM];
__device__ float g_fold[3 * 65 * H_DIM];

// ---------------- packed f32x2 helpers (sm_103a FFMA2) -----------------------
__device__ __forceinline__ ull fma2(ull a, ull b, ull c) {
    ull d;
    asm("fma.rn.f32x2 %0, %1, %2, %3;" : "=l"(d) : "l"(a), "l"(b), "l"(c));
    return d;
}
__device__ __forceinline__ ull pack2(float x, float y) {
    ull r; asm("mov.b64 %0, {%1, %2};" : "=l"(r) : "f"(x), "f"(y)); return r;
}
__device__ __forceinline__ float2 unpack2(ull v) {
    float lo, hi; asm("mov.b64 {%0, %1}, %2;" : "=f"(lo), "=f"(hi) : "l"(v));
    return make_float2(lo, hi);
}
__device__ __forceinline__ void red_add_v2(float* a, float x, float y) {
    asm volatile("red.global.add.v2.f32 [%0], {%1, %2};"
                 :: "l"(a), "f"(x), "f"(y) : "memory");
}
__device__ __forceinline__ float silu_f(float v) {
    float t;
    asm("tanh.approx.f32 %0, %1;" : "=f"(t) : "f"(0.5f * v));
    float hv = 0.5f * v;
    return fmaf(hv, t, hv);
}

// ---------------- fold prep ----------------------------------------------------
__global__ void prep_fold(const float* __restrict__ nw2_0,
                          const float* __restrict__ nb2_0,
                          const float* __restrict__ mlp_w1,
                          const float* __restrict__ nw1_1,
                          float* __restrict__ fold) {
    int m = blockIdx.y;
    const float* W = (m == 0) ? mlp_w1 : (m == 1) ? (mlp_w1 + 128 * H_DIM) : nw1_1;
    int row = blockIdx.x;
    int c = threadIdx.x;
    float s = 0.f;
    if (row < 64) {
#pragma unroll 8
        for (int j = 0; j < 128; j++) s += nw2_0[row * HID + j] * W[j * H_DIM + c];
    } else {
#pragma unroll 8
        for (int j = 0; j < 128; j++) s += nb2_0[j] * W[j * H_DIM + c];
    }
    fold[(m * 65 + row) * H_DIM + c] = s;
}

// ---------------- pack_all ------------------------------------------------------
__device__ __forceinline__ void pack_sec(ull* __restrict__ dst,
                                         const float* __restrict__ W,
                                         int nkp, int tid, int T) {
    for (int i = tid; i < nkp * 64; i += T) {
        int kp = i >> 6, c = i & 63;
        dst[i] = pack2(W[(2 * kp) * H_DIM + c], W[(2 * kp + 1) * H_DIM + c]);
    }
}

__global__ void pack_all(const float* __restrict__ mlp_w0,
                         const float* __restrict__ mlp_w1,
                         const float* __restrict__ edge_w0,
                         const float* __restrict__ edge_w1,
                         const float* __restrict__ nw1_0,
                         const float* __restrict__ nw1_1,
                         const float* __restrict__ fold,
                         const float* __restrict__ pos,
                         ull* __restrict__ wp,
                         float* __restrict__ pos4,
                         float* __restrict__ eagg,
                         float* __restrict__ cusum,
                         float* __restrict__ deg,
                         float* __restrict__ gsum) {
    int tid = blockIdx.x * blockDim.x + threadIdx.x;
    int T = gridDim.x * blockDim.x;

    pack_sec(wp + OFF_PAB,         mlp_w0,               64, tid, T);
    pack_sec(wp + OFF_PAB + 4096,  mlp_w0 + 128 * H_DIM, 64, tid, T);
    pack_sec(wp + OFF_E0,          edge_w0,              32, tid, T);
    pack_sec(wp + OFF_E0 + 2048,   mlp_w0 + 256 * H_DIM,  8, tid, T);
    pack_sec(wp + OFF_E1,          edge_w1,              32, tid, T);
    pack_sec(wp + OFF_E1 + 2048,   mlp_w1 + 256 * H_DIM,  8, tid, T);
    pack_sec(wp + OFF_N1,          nw1_0,                96, tid, T);
    pack_sec(wp + OFF_PRT,         fold,                 32, tid, T);
    pack_sec(wp + OFF_PRT + 2048,  fold + 65 * H_DIM,    32, tid, T);
    pack_sec(wp + OFF_N1L1,        fold + 130 * H_DIM,   32, tid, T);
    pack_sec(wp + OFF_N1L1 + 2048, nw1_1 + 128 * H_DIM,  32, tid, T);

    for (int i = tid; i < N_NODES; i += T)
        *(float4*)(pos4 + 4 * i) = make_float4(pos[3*i], pos[3*i+1], pos[3*i+2], 0.f);

    float4 z4 = make_float4(0.f, 0.f, 0.f, 0.f);
    for (int i = tid; i < (N_NODES * H_DIM) / 4; i += T) ((float4*)eagg)[i] = z4;
    for (int i = tid; i < (N_NODES * 3) / 4; i += T)     ((float4*)cusum)[i] = z4;
    for (int i = tid; i < N_NODES / 4; i += T)           ((float4*)deg)[i] = z4;
    for (int i = tid; i < (G_GRAPHS * H_DIM) / 4; i += T) ((float4*)gsum)[i] = z4;
}

// ---------------- smem weight copy ---------------------------------------------
__device__ __forceinline__ void copy_w(ull* s, const ull* g, int n_ull) {
    const ulonglong2* src = (const ulonglong2*)g;
    ulonglong2* dst = (ulonglong2*)s;
    for (int i = threadIdx.x; i < (n_ull >> 1); i += 256) dst[i] = src[i];
    __syncthreads();
}

// ---------------- layer-0 precompute: a=x@Wd, b=x@Ws, xn1=x@W1x ---------------
__global__ void __launch_bounds__(256, 2) precompute_ab(const float* __restrict__ x,
                                                        const ull* __restrict__ wpack,
                                                        float* __restrict__ a,
                                                        float* __restrict__ b,
                                                        float* __restrict__ xn1) {
    extern __shared__ ull swp[];                  // 12288 ull = 96KB
    {
        const ulonglong2* s1 = (const ulonglong2*)(wpack + OFF_PAB);
        ulonglong2* d1 = (ulonglong2*)swp;
        for (int i = threadIdx.x; i < 4096; i += 256) d1[i] = s1[i];
        const ulonglong2* s2 = (const ulonglong2*)(wpack + OFF_N1);
        ulonglong2* d2 = (ulonglong2*)(swp + 8192);
        for (int i = threadIdx.x; i < 2048; i += 256) d2[i] = s2[i];
        __syncthreads();
    }

    int lane = threadIdx.x & 31;
    int warp = (blockIdx.x * 256 + threadIdx.x) >> 5;
    int nw = gridDim.x * 8;
    const int NG = N_NODES / 4;
    const ull* s_wd = swp;
    const ull* s_ws = swp + 4096;
    const ull* s_wn = swp + 8192;

    for (int g = warp; g < NG; g += nw) {
        int nbase = g * 4;
        ull aC0[4], aC1[4], bC0[4], bC1[4], cC0[4], cC1[4];
#pragma unroll
        for (int t = 0; t < 4; t++) { aC0[t]=0; aC1[t]=0; bC0[t]=0; bC1[t]=0; cC0[t]=0; cC1[t]=0; }
#pragma unroll 4
        for (int q = 0; q < 32; q++) {
            ulonglong2 wd0 = *(const ulonglong2*)(s_wd + (2*q)   * 64 + 2*lane);
            ulonglong2 wd1 = *(const ulonglong2*)(s_wd + (2*q+1) * 64 + 2*lane);
            ulonglong2 ws0 = *(const ulonglong2*)(s_ws + (2*q)   * 64 + 2*lane);
            ulonglong2 ws1 = *(const ulonglong2*)(s_ws + (2*q+1) * 64 + 2*lane);
            ulonglong2 wn0 = *(const ulonglong2*)(s_wn + (2*q)   * 64 + 2*lane);
            ulonglong2 wn1 = *(const ulonglong2*)(s_wn + (2*q+1) * 64 + 2*lane);
#pragma unroll
            for (int t = 0; t < 4; t++) {
                ulonglong2 xp = *(const ulonglong2*)(x + (size_t)(nbase + t) * F_IN + 4 * q);
                aC0[t] = fma2(xp.x, wd0.x, aC0[t]); aC1[t] = fma2(xp.x, wd0.y, aC1[t]);
                aC0[t] = fma2(xp.y, wd1.x, aC0[t]); aC1[t] = fma2(xp.y, wd1.y, aC1[t]);
                bC0[t] = fma2(xp.x, ws0.x, bC0[t]); bC1[t] = fma2(xp.x, ws0.y, bC1[t]);
                bC0[t] = fma2(xp.y, ws1.x, bC0[t]); bC1[t] = fma2(xp.y, ws1.y, bC1[t]);
                cC0[t] = fma2(xp.x, wn0.x, cC0[t]); cC1[t] = fma2(xp.x, wn0.y, cC1[t]);
                cC0[t] = fma2(xp.y, wn1.x, cC0[t]); cC1[t] = fma2(xp.y, wn1.y, cC1[t]);
            }
        }
#pragma unroll
        for (int t = 0; t < 4; t++) {
            float2 va0 = unpack2(aC0[t]), va1 = unpack2(aC1[t]);
            float2 vb0 = unpack2(bC0[t]), vb1 = unpack2(bC1[t]);
            float2 vc0 = unpack2(cC0[t]), vc1 = unpack2(cC1[t]);
            *(float2*)(a + (size_t)(nbase + t) * H_DIM + 2*lane) =
                make_float2(va0.x + va0.y, va1.x + va1.y);
            *(float2*)(b + (size_t)(nbase + t) * H_DIM + 2*lane) =
                make_float2(vb0.x + vb0.y, vb1.x + vb1.y);
            *(float2*)(xn1 + (size_t)(nbase + t) * H_DIM + 2*lane) =
                make_float2(vc0.x + vc0.y, vc1.x + vc1.y);
        }
    }
}

// ---------------- FUSED node1 + layer-1 precompute -----------------------------
// step 1: t = silu(nb1 + xn1 + eagg@W1e)  -> global t AND per-warp smem
// step 2: a1 = t@A1 + ba, b1 = t@B1 + bb  (t read from smem)
// plus: pos update, eagg zeroing
__global__ void __launch_bounds__(256, 3) node1_pret(const float* __restrict__ xn1,
                                                     const ull* __restrict__ wpack,
                                                     const float* __restrict__ fold,
                                                     const float* __restrict__ nb1_0,
                                                     const float* __restrict__ posin,
                                                     const float* __restrict__ cusum,
                                                     const float* __restrict__ deg,
                                                     float* __restrict__ tglob,
                                                     float* __restrict__ a,
                                                     float* __restrict__ b,
                                                     float* __restrict__ posout,
                                                     float* __restrict__ eagg) {
    extern __shared__ ull swp[];      // A1(2048) | B1(2048) | W1e(2048) | t-stage(8*1KB)
    {
        const ulonglong2* s1 = (const ulonglong2*)(wpack + OFF_PRT);
        ulonglong2* d1 = (ulonglong2*)swp;
        for (int i = threadIdx.x; i < 2048; i += 256) d1[i] = s1[i];
        const ulonglong2* s2 = (const ulonglong2*)(wpack + OFF_N1 + 4096);
        ulonglong2* d2 = (ulonglong2*)(swp + 4096);
        for (int i = threadIdx.x; i < 1024; i += 256) d2[i] = s2[i];
        __syncthreads();
    }
    float* s_tall = (float*)(swp + 6144);

    int lane = threadIdx.x & 31;
    int wl = threadIdx.x >> 5;
    int warp = (blockIdx.x * 256 + threadIdx.x) >> 5;
    int nw = gridDim.x * 8;
    float* s_t = s_tall + wl * (4 * H_DIM);

    float nb0 = nb1_0[2*lane], nb1v = nb1_0[2*lane + 1];
    float ba0 = fold[64 * H_DIM + 2*lane],        ba1 = fold[64 * H_DIM + 2*lane + 1];
    float bb0 = fold[(65 + 64) * H_DIM + 2*lane], bb1 = fold[(65 + 64) * H_DIM + 2*lane + 1];
    const int NG = N_NODES / 4;

    for (int g = warp; g < NG; g += nw) {
        int nbase = g * 4;
        // ---- step 1: t = silu(nb1 + xn1 + eagg@W1e)
        {
            ull tC0[4], tC1[4];
#pragma unroll
            for (int t = 0; t < 4; t++) { tC0[t] = 0; tC1[t] = 0; }
#pragma unroll 4
            for (int q = 0; q < 16; q++) {
                ulonglong2 w0 = *(const ulonglong2*)(swp + 4096 + (2*q)   * 64 + 2*lane);
                ulonglong2 w1 = *(const ulonglong2*)(swp + 4096 + (2*q+1) * 64 + 2*lane);
#pragma unroll
                for (int t = 0; t < 4; t++) {
                    ulonglong2 ep = *(const ulonglong2*)(eagg + (size_t)(nbase + t) * H_DIM + 4 * q);
                    tC0[t] = fma2(ep.x, w0.x, tC0[t]); tC1[t] = fma2(ep.x, w0.y, tC1[t]);
                    tC0[t] = fma2(ep.y, w1.x, tC0[t]); tC1[t] = fma2(ep.y, w1.y, tC1[t]);
                }
            }
#pragma unroll
            for (int t = 0; t < 4; t++) {
                float2 xv = *(const float2*)(xn1 + (size_t)(nbase + t) * H_DIM + 2*lane);
                float2 v0 = unpack2(tC0[t]), v1 = unpack2(tC1[t]);
                float t0 = silu_f(nb0 + xv.x + v0.x + v0.y);
                float t1 = silu_f(nb1v + xv.y + v1.x + v1.y);
                float2 tv = make_float2(t0, t1);
                *(float2*)(tglob + (size_t)(nbase + t) * H_DIM + 2*lane) = tv;
                *(float2*)(s_t + t * H_DIM + 2*lane) = tv;
                // zero eagg (this warp is the only reader of these rows)
                *(float2*)(eagg + (size_t)(nbase + t) * H_DIM + 2*lane) = make_float2(0.f, 0.f);
            }
        }
        __syncwarp();

        // ---- step 2: a1 = t@A1 + ba, b1 = t@B1 + bb (t from smem)
        ull aC0[4], aC1[4], bC0[4], bC1[4];
#pragma unroll
        for (int t = 0; t < 4; t++) { aC0[t]=0; aC1[t]=0; bC0[t]=0; bC1[t]=0; }
#pragma unroll 4
        for (int q = 0; q < 16; q++) {
            ulonglong2 wa0 = *(const ulonglong2*)(swp + (2*q)   * 64 + 2*lane);
            ulonglong2 wa1 = *(const ulonglong2*)(swp + (2*q+1) * 64 + 2*lane);
            ulonglong2 wb0 = *(const ulonglong2*)(swp + 2048 + (2*q)   * 64 + 2*lane);
            ulonglong2 wb1 = *(const ulonglong2*)(swp + 2048 + (2*q+1) * 64 + 2*lane);
#pragma unroll
            for (int t = 0; t < 4; t++) {
                ulonglong2 tp = *(const ulonglong2*)(s_t + t * H_DIM + 4 * q);
                aC0[t] = fma2(tp.x, wa0.x, aC0[t]); aC1[t] = fma2(tp.x, wa0.y, aC1[t]);
                aC0[t] = fma2(tp.y, wa1.x, aC0[t]); aC1[t] = fma2(tp.y, wa1.y, aC1[t]);
                bC0[t] = fma2(tp.x, wb0.x, bC0[t]); bC1[t] = fma2(tp.x, wb0.y, bC1[t]);
                bC0[t] = fma2(tp.y, wb1.x, bC0[t]); bC1[t] = fma2(tp.y, wb1.y, bC1[t]);
            }
        }
        __syncwarp();
#pragma unroll
        for (int t = 0; t < 4; t++) {
            float2 va0 = unpack2(aC0[t]), va1 = unpack2(aC1[t]);
            float2 vb0 = unpack2(bC0[t]), vb1 = unpack2(bC1[t]);
            *(float2*)(a + (size_t)(nbase + t) * H_DIM + 2*lane) =
                make_float2(ba0 + va0.x + va0.y, ba1 + va1.x + va1.y);
            *(float2*)(b + (size_t)(nbase + t) * H_DIM + 2*lane) =
                make_float2(bb0 + vb0.x + vb0.y, bb1 + vb1.x + vb1.y);
        }
        if (lane < 4) {
            int node = nbase + lane;
            float dg = fmaxf(deg[node], 1.0f);
            float4 pv = *(const float4*)(posin + 4 * node);
            *(float4*)(posout + 4 * node) = make_float4(
                pv.x + cusum[node * 3 + 0] / dg,
                pv.y + cusum[node * 3 + 1] / dg,
                pv.z + cusum[node * 3 + 2] / dg, 0.f);
        }
    }
}

// ---------------- edge kernel: EXACT R12/R14 form -----------------------------
template<int DO_COORD>
__global__ void __launch_bounds__(256, 2) edge_kernel(const float* __restrict__ pos4,
                                                      const int* __restrict__ eidx,
                                                      const float* __restrict__ edge_attr,
                                                      const ull* __restrict__ wpack,
                                                      const float* __restrict__ mlp_w,
                                                      const float* __restrict__ edge_b,
                                                      const float* __restrict__ coord_w,
                                                      const float* __restrict__ coord_b,
                                                      const float* __restrict__ a,
                                                      const float* __restrict__ b,
                                                      float* __restrict__ eagg,
                                                      float* __restrict__ cusum,
                                                      float* __restrict__ deg) {
    extern __shared__ ull sm_u[];
    ull* s_wp     = sm_u;
    ull* s_wattrP = sm_u + 2048;
    float* s_hall = (float*)(sm_u + 2560);
    float* s_eall = s_hall + 8 * EPG * H_DIM;
    copy_w(sm_u, wpack, 2560);

    int lane = threadIdx.x & 31, k0 = lane * 2;
    int wl = threadIdx.x >> 5;
    int warp = (blockIdx.x * 256 + threadIdx.x) >> 5;
    int nw = gridDim.x * 8;
    float* s_h  = s_hall + wl * (EPG * H_DIM);
    float* s_ea = s_eall + wl * (EPG * D_ATTR);

    float wr0 = mlp_w[(2 * F_IN + D_ATTR) * H_DIM + k0];
    float wr1 = mlp_w[(2 * F_IN + D_ATTR) * H_DIM + k0 + 1];
    float eb0 = edge_b[k0], eb1 = edge_b[k0 + 1];
    float cw0 = coord_w[k0], cw1 = coord_w[k0 + 1];
    float cb = coord_b[0];

    const int NGROUPS = N_EDGES / EPG;
    for (int g = warp; g < NGROUPS; g += nw) {
        int ebase = g * EPG;

        {
            const float4* gattr = (const float4*)(edge_attr + (size_t)ebase * D_ATTR);
            ((float4*)s_ea)[lane]      = gattr[lane];
            ((float4*)s_ea)[lane + 32] = gattr[lane + 32];
        }
        __syncwarp();

        int dsts[EPG];
        float mydx = 0.f, mydy = 0.f, mydz = 0.f;

#pragma unroll
        for (int half = 0; half < 4; half++) {
            int4 s4 = *(const int4*)(eidx + ebase + 4 * half);
            int4 d4 = *(const int4*)(eidx + N_EDGES + ebase + 4 * half);
            int ss[4] = {s4.x, s4.y, s4.z, s4.w};
            int dd[4] = {d4.x, d4.y, d4.z, d4.w};
            dsts[4*half+0] = d4.x; dsts[4*half+1] = d4.y;
            dsts[4*half+2] = d4.z; dsts[4*half+3] = d4.w;
            float b0[4], b1[4];
            ull hk0[4], hk1[4];
#pragma unroll
            for (int t = 0; t < 4; t++) {
                int ei = half * 4 + t;
                float4 pd = *(const float4*)(pos4 + 4 * dd[t]);
                float4 ps = *(const float4*)(pos4 + 4 * ss[t]);
                float dx = pd.x - ps.x, dy = pd.y - ps.y, dz = pd.z - ps.z;
                if (lane == ei) { mydx = dx; mydy = dy; mydz = dz; }
                float radial = dx * dx + dy * dy + dz * dz;
                float2 av = *(const float2*)(a + (size_t)dd[t] * H_DIM + k0);
                float2 bv = *(const float2*)(b + (size_t)ss[t] * H_DIM + k0);
                b0[t] = av.x + bv.x + radial * wr0;
                b1[t] = av.y + bv.y + radial * wr1;
                hk0[t] = 0; hk1[t] = 0;
            }
#pragma unroll
            for (int q = 0; q < 2; q++) {
                ulonglong2 w0 = *(const ulonglong2*)(s_wattrP + (4*q+0)*64 + 2*lane);
                ulonglong2 w1 = *(const ulonglong2*)(s_wattrP + (4*q+1)*64 + 2*lane);
                ulonglong2 w2 = *(const ulonglong2*)(s_wattrP + (4*q+2)*64 + 2*lane);
                ulonglong2 w3 = *(const ulonglong2*)(s_wattrP + (4*q+3)*64 + 2*lane);
#pragma unroll
                for (int t = 0; t < 4; t++) {
                    int ei = half * 4 + t;
                    ulonglong2 eaA = *(const ulonglong2*)(s_ea + ei * D_ATTR + 8*q);
                    ulonglong2 eaB = *(const ulonglong2*)(s_ea + ei * D_ATTR + 8*q + 4);
                    hk0[t] = fma2(eaA.x, w0.x, hk0[t]); hk1[t] = fma2(eaA.x, w0.y, hk1[t]);
                    hk0[t] = fma2(eaA.y, w1.x, hk0[t]); hk1[t] = fma2(eaA.y, w1.y, hk1[t]);
                    hk0[t] = fma2(eaB.x, w2.x, hk0[t]); hk1[t] = fma2(eaB.x, w2.y, hk1[t]);
                    hk0[t] = fma2(eaB.y, w3.x, hk0[t]); hk1[t] = fma2(eaB.y, w3.y, hk1[t]);
                }
            }
#pragma unroll
            for (int t = 0; t < 4; t++) {
                float2 v0 = unpack2(hk0[t]), v1 = unpack2(hk1[t]);
                float h0 = silu_f(b0[t] + v0.x + v0.y);
                float h1 = silu_f(b1[t] + v1.x + v1.y);
                *(float2*)(s_h + (half * 4 + t) * H_DIM + k0) = make_float2(h0, h1);
            }
        }
        __syncwarp();

        ull acc0[EPG], acc1[EPG];
#pragma unroll
        for (int t = 0; t < EPG; t++) { acc0[t] = 0; acc1[t] = 0; }
#pragma unroll 2
        for (int q = 0; q < 16; q++) {
            ulonglong2 wA = *(const ulonglong2*)(s_wp + (2*q)   * 64 + 2*lane);
            ulonglong2 wB = *(const ulonglong2*)(s_wp + (2*q+1) * 64 + 2*lane);
#pragma unroll
            for (int t = 0; t < EPG; t++) {
                ulonglong2 hv = *(const ulonglong2*)(s_h + t * H_DIM + 4 * q);
                acc0[t] = fma2(hv.x, wA.x, acc0[t]); acc1[t] = fma2(hv.x, wA.y, acc1[t]);
                acc0[t] = fma2(hv.y, wB.x, acc0[t]); acc1[t] = fma2(hv.y, wB.y, acc1[t]);
            }
        }
        __syncwarp();

        float myss = 0.f;
#pragma unroll
        for (int t = 0; t < EPG; t++) {
            float2 v0 = unpack2(acc0[t]), v1 = unpack2(acc1[t]);
            float e0 = silu_f(eb0 + v0.x + v0.y);
            float e1 = silu_f(eb1 + v1.x + v1.y);
            red_add_v2(eagg + (size_t)dsts[t] * H_DIM + k0, e0, e1);
            if (DO_COORD) {
                float p = e0 * cw0 + e1 * cw1;
                p += __shfl_xor_sync(0xffffffffu, p, 16);
                p += __shfl_xor_sync(0xffffffffu, p, 8);
                p += __shfl_xor_sync(0xffffffffu, p, 4);
                p += __shfl_xor_sync(0xffffffffu, p, 2);
                p += __shfl_xor_sync(0xffffffffu, p, 1);
                if (lane == t) myss = silu_f(p + cb);
            }
        }
        if (DO_COORD && lane < EPG) {
            int d3 = dsts[lane] * 3;
            atomicAdd(cusum + d3 + 0, mydx * myss);
            atomicAdd(cusum + d3 + 1, mydy * myss);
            atomicAdd(cusum + d3 + 2, mydz * myss);
            atomicAdd(deg + dsts[lane], 1.0f);
        }
    }
}

// ---------------- node1 layer 1 + fused pooling -------------------------------
__global__ void __launch_bounds__(256, 3) node1_l1_pool(const float* __restrict__ tin,
                                                        const float* __restrict__ eagg,
                                                        const ull* __restrict__ wpack,
                                                        const float* __restrict__ fold,
                                                        const float* __restrict__ nb1_1,
                                                        const int* __restrict__ batch,
                                                        float* __restrict__ gsum) {
    extern __shared__ ull swp[];                   // 4096 ull = 32KB
    copy_w(swp, wpack + OFF_N1L1, 4096);

    int lane = threadIdx.x & 31;
    int warp = (blockIdx.x * 256 + threadIdx.x) >> 5;
    int nw = gridDim.x * 8;
    float bn0 = fold[(130 + 64) * H_DIM + 2*lane]     + nb1_1[2*lane];
    float bn1 = fold[(130 + 64) * H_DIM + 2*lane + 1] + nb1_1[2*lane + 1];
    const int NG = N_NODES / 8;

    for (int g = warp; g < NG; g += nw) {
        int nbase = g * 8;
        ull a0[8], a1[8];
#pragma unroll
        for (int t = 0; t < 8; t++) { a0[t] = 0; a1[t] = 0; }
#pragma unroll 4
        for (int q = 0; q < 16; q++) {
            ulonglong2 w0 = *(const ulonglong2*)(swp + (2*q)   * 64 + 2*lane);
            ulonglong2 w1 = *(const ulonglong2*)(swp + (2*q+1) * 64 + 2*lane);
#pragma unroll
            for (int t = 0; t < 8; t++) {
                ulonglong2 tp = *(const ulonglong2*)(tin + (size_t)(nbase + t) * H_DIM + 4 * q);
                a0[t] = fma2(tp.x, w0.x, a0[t]); a1[t] = fma2(tp.x, w0.y, a1[t]);
                a0[t] = fma2(tp.y, w1.x, a0[t]); a1[t] = fma2(tp.y, w1.y, a1[t]);
            }
        }
#pragma unroll 4
        for (int q = 0; q < 16; q++) {
            ulonglong2 w0 = *(const ulonglong2*)(swp + 2048 + (2*q)   * 64 + 2*lane);
            ulonglong2 w1 = *(const ulonglong2*)(swp + 2048 + (2*q+1) * 64 + 2*lane);
#pragma unroll
            for (int t = 0; t < 8; t++) {
                ulonglong2 ep = *(const ulonglong2*)(eagg + (size_t)(nbase + t) * H_DIM + 4 * q);
                a0[t] = fma2(ep.x, w0.x, a0[t]); a1[t] = fma2(ep.x, w0.y, a1[t]);
                a0[t] = fma2(ep.y, w1.x, a0[t]); a1[t] = fma2(ep.y, w1.y, a1[t]);
            }
        }
        int bfirst = batch[nbase], blast = batch[nbase + 7];
        if (bfirst == blast) {
            float s0 = 0.f, s1 = 0.f;
#pragma unroll
            for (int t = 0; t < 8; t++) {
                float2 v0 = unpack2(a0[t]), v1 = unpack2(a1[t]);
                s0 += silu_f(bn0 + v0.x + v0.y);
                s1 += silu_f(bn1 + v1.x + v1.y);
            }
            red_add_v2(gsum + bfirst * H_DIM + 2 * lane, s0, s1);
        } else {
#pragma unroll
            for (int t = 0; t < 8; t++) {
                float2 v0 = unpack2(a0[t]), v1 = unpack2(a1[t]);
                float t0 = silu_f(bn0 + v0.x + v0.y);
                float t1 = silu_f(bn1 + v1.x + v1.y);
                red_add_v2(gsum + batch[nbase + t] * H_DIM + 2 * lane, t0, t1);
            }
        }
    }
}

// ---------------- final: count + fold layer1 w2 + output MLP ------------------
__global__ void final_kernel(const float* __restrict__ gsum,
                             const int* __restrict__ batch,
                             const float* __restrict__ nw2,
                             const float* __restrict__ nb2,
                             const float* __restrict__ w1,
                             const float* __restrict__ b1,
                             const float* __restrict__ w2,
                             const float* __restrict__ b2,
                             float* __restrict__ out) {
    int g = blockIdx.x;
    int tx = threadIdx.x;   // 128 threads
    __shared__ float sm64[H_DIM];
    __shared__ float sg[HID];
    __shared__ float st[HID];
    __shared__ int scnt;
    if (tx == 0) scnt = 0;
    __syncthreads();
    int local = 0;
    for (int i = tx; i < N_NODES; i += 128) local += (batch[i] == g);
#pragma unroll
    for (int off = 16; off; off >>= 1) local += __shfl_xor_sync(0xffffffffu, local, off);
    if ((tx & 31) == 0) atomicAdd(&scnt, local);
    __syncthreads();
    float cnt = fmaxf((float)scnt, 1.0f);
    if (tx < H_DIM) sm64[tx] = gsum[g * H_DIM + tx] / cnt;
    __syncthreads();
    float gv = nb2[tx];
#pragma unroll 8
    for (int k = 0; k < H_DIM; k++) gv += sm64[k] * nw2[k * HID + tx];
    sg[tx] = fmaxf(gv, 0.0f);
    __syncthreads();
    float acc = b1[tx];
#pragma unroll 8
    for (int j = 0; j < HID; j++) acc += sg[j] * w1[j * HID + tx];
    st[tx] = fmaxf(acc, 0.0f);
    __syncthreads();
    if (tx < OUT_DIM) {
        float o = b2[tx];
#pragma unroll 8
        for (int k = 0; k < HID; k++) o += st[k] * w2[k * OUT_DIM + tx];
        out[g * OUT_DIM + tx] = o;
    }
}

// ---------------- launch --------------------------------------------------------
extern "C" void kernel_launch(void* const* d_in, const int* in_sizes, int n_in,
                              void* d_out, int out_size) {
    const float* x         = (const float*)d_in[0];
    const float* pos       = (const float*)d_in[1];
    const float* edge_attr = (const float*)d_in[2];
    const int* eidx        = (const int*)d_in[3];
    const int* batch       = (const int*)d_in[4];

    const float* mlp_w[2]  = {(const float*)d_in[5],  (const float*)d_in[14]};
    const float* edge_w[2] = {(const float*)d_in[6],  (const float*)d_in[15]};
    const float* edge_b[2] = {(const float*)d_in[7],  (const float*)d_in[16]};
    const float* coord_w[2]= {(const float*)d_in[8],  (const float*)d_in[17]};
    const float* coord_b[2]= {(const float*)d_in[9],  (const float*)d_in[18]};
    const float* nw1[2]    = {(const float*)d_in[10], (const float*)d_in[19]};
    const float* nb1[2]    = {(const float*)d_in[11], (const float*)d_in[20]};
    const float* nw2[2]    = {(const float*)d_in[12], (const float*)d_in[21]};
    const float* nb2[2]    = {(const float*)d_in[13], (const float*)d_in[22]};
    const float* ow1 = (const float*)d_in[23];
    const float* ob1 = (const float*)d_in[24];
    const float* ow2 = (const float*)d_in[25];
    const float* ob2 = (const float*)d_in[26];
    float* out = (float*)d_out;

    float *pa, *pb, *pe, *pt, *pxn, *pc, *pd, *pp4a, *pp4b, *pgs, *pf;
    ull* pw;
    cudaGetSymbolAddress((void**)&pa, g_a);
    cudaGetSymbolAddress((void**)&pb, g_b);
    cudaGetSymbolAddress((void**)&pe, g_eagg);
    cudaGetSymbolAddress((void**)&pt, g_t);
    cudaGetSymbolAddress((void**)&pxn, g_xn1);
    cudaGetSymbolAddress((void**)&pc, g_cusum);
    cudaGetSymbolAddress((void**)&pd, g_deg);
    cudaGetSymbolAddress((void**)&pp4a, g_pos4a);
    cudaGetSymbolAddress((void**)&pp4b, g_pos4b);
    cudaGetSymbolAddress((void**)&pgs, g_gsum);
    cudaGetSymbolAddress((void**)&pf, g_fold);
    cudaGetSymbolAddress((void**)&pw, g_wpack);

    const int PRE_SMEM  = 12288 * (int)sizeof(ull);  // 96KB
    const int NPT_SMEM  = 6144 * (int)sizeof(ull) + 8 * 4 * H_DIM * (int)sizeof(float); // 56KB
    const int N1L1_SMEM = 4096 * (int)sizeof(ull);   // 32KB
    const int EDGE_SMEM = 2560 * (int)sizeof(ull)
                        + 8 * EPG * H_DIM * (int)sizeof(float)
                        + 8 * EPG * D_ATTR * (int)sizeof(float);   // 60KB
    cudaFuncSetAttribute(precompute_ab, cudaFuncAttributeMaxDynamicSharedMemorySize, PRE_SMEM);
    cudaFuncSetAttribute(node1_pret, cudaFuncAttributeMaxDynamicSharedMemorySize, NPT_SMEM);
    cudaFuncSetAttribute(node1_l1_pool, cudaFuncAttributeMaxDynamicSharedMemorySize, N1L1_SMEM);
    cudaFuncSetAttribute(edge_kernel<1>, cudaFuncAttributeMaxDynamicSharedMemorySize, EDGE_SMEM);
    cudaFuncSetAttribute(edge_kernel<0>, cudaFuncAttributeMaxDynamicSharedMemorySize, EDGE_SMEM);

    // ---------------- prep: 2 launches total
    prep_fold<<<dim3(65, 3), 64>>>(nw2[0], nb2[0], mlp_w[1], nw1[1], pf);
    pack_all<<<256, 256>>>(mlp_w[0], mlp_w[1], edge_w[0], edge_w[1], nw1[0], nw1[1],
                           pf, pos, pw, pp4a, pe, pc, pd, pgs);

    // ---------------- layer 0
    precompute_ab<<<296, 256, PRE_SMEM>>>(x, pw, pa, pb, pxn);
    edge_kernel<1><<<296, 256, EDGE_SMEM>>>(pp4a, eidx, edge_attr, pw + OFF_E0, mlp_w[0],
                                            edge_b[0], coord_w[0], coord_b[0],
                                            pa, pb, pe, pc, pd);

    // ---------------- fused node1 + layer-1 precompute
    node1_pret<<<444, 256, NPT_SMEM>>>(pxn, pw, pf, nb1[0], pp4a, pc, pd,
                                       pt, pa, pb, pp4b, pe);

    // ---------------- layer 1
    edge_kernel<0><<<296, 256, EDGE_SMEM>>>(pp4b, eidx, edge_attr, pw + OFF_E1, mlp_w[1],
                                            edge_b[1], coord_w[1], coord_b[1],
                                            pa, pb, pe, pc, pd);
    node1_l1_pool<<<444, 256, N1L1_SMEM>>>(pt, pe, pw, pf, nb1[1], batch, pgs);

    // ---------------- output
    final_kernel<<<G_GRAPHS, HID>>>(pgs, batch, nw2[1], nb2[1], ow1, ob1, ow2, ob2, out);
}